// round 2
// baseline (speedup 1.0000x reference)
#include <cuda_runtime.h>
#include <cuda_bf16.h>
#include <cstdint>

// Problem constants
#define Bb 4
#define Ss 2048
#define Dd 1024
#define Hh 16
#define HD 64
#define NTOK (Bb * Ss)          // 8192
#define QKV_LD 3072             // fused Q|K|V row stride

// ---------------- scratch (no allocation allowed -> __device__ globals) ----
__device__ float g_Wpack[Dd * QKV_LD];     // [k][n] n: 0..1023 Q, 1024.. K, 2048.. V
__device__ float g_WoT[Dd * Dd];           // [k][n] = Wo[n][k]
__device__ float g_QKV[(size_t)NTOK * QKV_LD];   // 96 MB
__device__ float g_Obuf[(size_t)NTOK * Dd];      // 32 MB

// ---------------- weight pack ---------------------------------------------
__global__ void pack_weights(const float* __restrict__ Wq,
                             const float* __restrict__ Wk,
                             const float* __restrict__ Wv,
                             const float* __restrict__ Wo)
{
    const int total1 = Dd * QKV_LD;
    for (int idx = blockIdx.x * blockDim.x + threadIdx.x; idx < total1;
         idx += gridDim.x * blockDim.x) {
        int k = idx / QKV_LD;
        int n = idx % QKV_LD;
        int sec = n >> 10;            // 0=Q 1=K 2=V
        int c = n & 1023;
        int h = c >> 6;
        int j = c & 63;
        const float* W = (sec == 0) ? Wq : (sec == 1) ? Wk : Wv;
        g_Wpack[idx] = W[h * (Dd * HD) + k * HD + j];
    }
    const int total2 = Dd * Dd;
    for (int idx = blockIdx.x * blockDim.x + threadIdx.x; idx < total2;
         idx += gridDim.x * blockDim.x) {
        int k = idx / Dd;
        int n = idx % Dd;
        g_WoT[idx] = Wo[n * Dd + k];  // coalesced write, strided read
    }
}

// ---------------- SGEMM 128x128x8, double buffered, 8x8 microtile ----------
// C[m][n] = sum_k A[m][k] * B[k][n] (+ bias[n])
__global__ __launch_bounds__(256, 2)
void sgemm(const float* __restrict__ A, const float* __restrict__ B,
           float* __restrict__ C, const float* __restrict__ bias,
           int M, int N, int K, int lda, int ldb, int ldc)
{
    __shared__ float As[2][8][132];   // transposed: As[k][m]
    __shared__ float Bs[2][8][132];   // Bs[k][n]

    const int tid = threadIdx.x;
    const int bm = blockIdx.y * 128;
    const int bn = blockIdx.x * 128;

    // A tile load map: 128 rows x 8 k = 256 float4
    const int arow = tid >> 1;
    const int acol = (tid & 1) * 4;
    const float* Aptr = A + (size_t)(bm + arow) * lda + acol;

    // B tile load map: 8 k x 128 n = 256 float4
    const int brow = tid >> 5;
    const int bcol = (tid & 31) * 4;
    const float* Bptr = B + (size_t)brow * ldb + bn + bcol;

    const int tx = tid & 15;
    const int ty = tid >> 4;

    float acc[8][8];
#pragma unroll
    for (int i = 0; i < 8; i++)
#pragma unroll
        for (int j = 0; j < 8; j++) acc[i][j] = 0.f;

    // prologue
    float4 av = *(const float4*)Aptr;
    float4 bv = *(const float4*)Bptr;
    As[0][acol + 0][arow] = av.x;
    As[0][acol + 1][arow] = av.y;
    As[0][acol + 2][arow] = av.z;
    As[0][acol + 3][arow] = av.w;
    *(float4*)&Bs[0][brow][bcol] = bv;
    __syncthreads();

    const int ntiles = K >> 3;
    int buf = 0;
    for (int kt = 0; kt < ntiles; ++kt) {
        float4 an, bn4;
        const bool more = (kt + 1 < ntiles);
        if (more) {
            an = *(const float4*)(Aptr + (kt + 1) * 8);
            bn4 = *(const float4*)(Bptr + (size_t)(kt + 1) * 8 * ldb);
        }
#pragma unroll
        for (int kk = 0; kk < 8; ++kk) {
            float a[8], b[8];
            *(float4*)&a[0] = *(const float4*)&As[buf][kk][ty * 8];
            *(float4*)&a[4] = *(const float4*)&As[buf][kk][ty * 8 + 4];
            *(float4*)&b[0] = *(const float4*)&Bs[buf][kk][tx * 8];
            *(float4*)&b[4] = *(const float4*)&Bs[buf][kk][tx * 8 + 4];
#pragma unroll
            for (int i = 0; i < 8; i++)
#pragma unroll
                for (int j = 0; j < 8; j++) acc[i][j] += a[i] * b[j];
        }
        if (more) {
            buf ^= 1;
            As[buf][acol + 0][arow] = an.x;
            As[buf][acol + 1][arow] = an.y;
            As[buf][acol + 2][arow] = an.z;
            As[buf][acol + 3][arow] = an.w;
            *(float4*)&Bs[buf][brow][bcol] = bn4;
            __syncthreads();
        }
    }

    // epilogue
    const int crow = bm + ty * 8;
    const int ccol = bn + tx * 8;
    float bvals[8];
#pragma unroll
    for (int j = 0; j < 8; j++) bvals[j] = bias ? bias[ccol + j] : 0.f;
#pragma unroll
    for (int i = 0; i < 8; i++) {
        float4 o0 = make_float4(acc[i][0] + bvals[0], acc[i][1] + bvals[1],
                                acc[i][2] + bvals[2], acc[i][3] + bvals[3]);
        float4 o1 = make_float4(acc[i][4] + bvals[4], acc[i][5] + bvals[5],
                                acc[i][6] + bvals[6], acc[i][7] + bvals[7]);
        *(float4*)&C[(size_t)(crow + i) * ldc + ccol] = o0;
        *(float4*)&C[(size_t)(crow + i) * ldc + ccol + 4] = o1;
    }
}

// ---------------- flash attention (causal) --------------------------------
// grid: (S/128, B*H). 256 threads. 128 q-rows x 128 k-cols tiles, d=64.
#define AT_BM 128
#define AT_BN 128
#define QT_LD 132      // padded row stride for transposed Q/K and P
#define VS_LD 68

__global__ __launch_bounds__(256, 1)
void attn_kernel(const float* __restrict__ QKV, float* __restrict__ O)
{
    extern __shared__ float sm[];
    float* Qt = sm;                       // [64][132]  Qt[k*132 + row]
    float* Kt = Qt + HD * QT_LD;          // [64][132]
    float* Vs = Kt + HD * QT_LD;          // [128][68]  Vs[kr*68 + c]
    float* Ps = Vs + AT_BN * VS_LD;       // [128][132] Ps[row*132 + kc]

    const int tid = threadIdx.x;
    const int tx = tid & 15;
    const int ty = tid >> 4;

    // heavy tiles (large qt) first for load balance
    const int qt = (gridDim.x - 1) - blockIdx.x;
    const int bh = blockIdx.y;
    const int b = bh / Hh;
    const int h = bh % Hh;

    const float scale = 0.125f;  // 1/sqrt(64)
    const int q0 = qt * AT_BM;

    // load Q tile transposed
    {
        const float* Qg = QKV + ((size_t)(b * Ss + q0)) * QKV_LD + h * HD;
#pragma unroll
        for (int i = 0; i < 8; ++i) {
            int f = tid + i * 256;
            int r = f >> 4;
            int c4 = (f & 15) << 2;
            float4 v = *(const float4*)(Qg + (size_t)r * QKV_LD + c4);
            Qt[(c4 + 0) * QT_LD + r] = v.x;
            Qt[(c4 + 1) * QT_LD + r] = v.y;
            Qt[(c4 + 2) * QT_LD + r] = v.z;
            Qt[(c4 + 3) * QT_LD + r] = v.w;
        }
    }

    float m[8], l[8], acc[8][4];
#pragma unroll
    for (int r = 0; r < 8; r++) {
        m[r] = -1e30f;
        l[r] = 0.f;
#pragma unroll
        for (int c = 0; c < 4; c++) acc[r][c] = 0.f;
    }

    const int row_base = ty * 8;

    for (int jt = 0; jt <= qt; ++jt) {
        const int k0 = jt * AT_BN;
        const float* Kg = QKV + ((size_t)(b * Ss + k0)) * QKV_LD + 1024 + h * HD;
        const float* Vg = QKV + ((size_t)(b * Ss + k0)) * QKV_LD + 2048 + h * HD;

        __syncthreads();   // previous PV done (and Q tile stored on first iter)
#pragma unroll
        for (int i = 0; i < 8; ++i) {
            int f = tid + i * 256;
            int r = f >> 4;
            int c4 = (f & 15) << 2;
            float4 kv = *(const float4*)(Kg + (size_t)r * QKV_LD + c4);
            Kt[(c4 + 0) * QT_LD + r] = kv.x;
            Kt[(c4 + 1) * QT_LD + r] = kv.y;
            Kt[(c4 + 2) * QT_LD + r] = kv.z;
            Kt[(c4 + 3) * QT_LD + r] = kv.w;
            float4 vv = *(const float4*)(Vg + (size_t)r * QKV_LD + c4);
            *(float4*)&Vs[r * VS_LD + c4] = vv;
        }
        __syncthreads();

        // S = Q K^T
        float s[8][8];
#pragma unroll
        for (int i = 0; i < 8; i++)
#pragma unroll
            for (int j = 0; j < 8; j++) s[i][j] = 0.f;
#pragma unroll
        for (int kk = 0; kk < HD; ++kk) {
            float a[8], bb[8];
            *(float4*)&a[0] = *(const float4*)&Qt[kk * QT_LD + row_base];
            *(float4*)&a[4] = *(const float4*)&Qt[kk * QT_LD + row_base + 4];
            *(float4*)&bb[0] = *(const float4*)&Kt[kk * QT_LD + tx * 8];
            *(float4*)&bb[4] = *(const float4*)&Kt[kk * QT_LD + tx * 8 + 4];
#pragma unroll
            for (int i = 0; i < 8; i++)
#pragma unroll
                for (int j = 0; j < 8; j++) s[i][j] += a[i] * bb[j];
        }

        const bool diag = (jt == qt);
#pragma unroll
        for (int r = 0; r < 8; r++) {
            const int qrow = q0 + row_base + r;
            float mx = -1e30f;
#pragma unroll
            for (int c = 0; c < 8; c++) {
                float sv = s[r][c] * scale;
                if (diag && (k0 + tx * 8 + c > qrow)) sv = -1e30f;
                s[r][c] = sv;
                mx = fmaxf(mx, sv);
            }
#pragma unroll
            for (int off = 1; off < 16; off <<= 1)
                mx = fmaxf(mx, __shfl_xor_sync(0xffffffffu, mx, off));
            const float mnew = fmaxf(m[r], mx);
            float sum = 0.f;
#pragma unroll
            for (int c = 0; c < 8; c++) {
                float p = __expf(s[r][c] - mnew);
                s[r][c] = p;
                sum += p;
            }
#pragma unroll
            for (int off = 1; off < 16; off <<= 1)
                sum += __shfl_xor_sync(0xffffffffu, sum, off);
            const float alpha = __expf(m[r] - mnew);
            l[r] = l[r] * alpha + sum;
            m[r] = mnew;
#pragma unroll
            for (int c = 0; c < 4; c++) acc[r][c] *= alpha;
            *(float4*)&Ps[(row_base + r) * QT_LD + tx * 8] =
                make_float4(s[r][0], s[r][1], s[r][2], s[r][3]);
            *(float4*)&Ps[(row_base + r) * QT_LD + tx * 8 + 4] =
                make_float4(s[r][4], s[r][5], s[r][6], s[r][7]);
        }
        __syncthreads();

        // O += P @ V   (thread: rows ty*8..+8, cols tx*4..+4)
#pragma unroll 4
        for (int kc = 0; kc < AT_BN; ++kc) {
            float4 vv = *(const float4*)&Vs[kc * VS_LD + tx * 4];
#pragma unroll
            for (int r = 0; r < 8; r++) {
                float p = Ps[(row_base + r) * QT_LD + kc];
                acc[r][0] += p * vv.x;
                acc[r][1] += p * vv.y;
                acc[r][2] += p * vv.z;
                acc[r][3] += p * vv.w;
            }
        }
    }

    // epilogue: normalize and write O[b, s, h*64 + c]
#pragma unroll
    for (int r = 0; r < 8; r++) {
        const float inv = 1.f / l[r];
        float4 o = make_float4(acc[r][0] * inv, acc[r][1] * inv,
                               acc[r][2] * inv, acc[r][3] * inv);
        *(float4*)&O[((size_t)(b * Ss + q0 + row_base + r)) * Dd + h * HD + tx * 4] = o;
    }
}

// ---------------- launch ----------------------------------------------------
extern "C" void kernel_launch(void* const* d_in, const int* in_sizes, int n_in,
                              void* d_out, int out_size)
{
    (void)in_sizes; (void)n_in; (void)out_size;
    const float* q  = (const float*)d_in[0];
    const float* k  = (const float*)d_in[1];
    const float* v  = (const float*)d_in[2];
    const float* Wq = (const float*)d_in[3];
    const float* Wk = (const float*)d_in[4];
    const float* Wv = (const float*)d_in[5];
    const float* Wo = (const float*)d_in[6];
    const float* bo = (const float*)d_in[7];
    float* out = (float*)d_out;

    float *Wpack, *WoT, *QKV, *Obuf;
    cudaGetSymbolAddress((void**)&Wpack, g_Wpack);
    cudaGetSymbolAddress((void**)&WoT, g_WoT);
    cudaGetSymbolAddress((void**)&QKV, g_QKV);
    cudaGetSymbolAddress((void**)&Obuf, g_Obuf);

    pack_weights<<<1024, 256>>>(Wq, Wk, Wv, Wo);

    dim3 gProj(Dd / 128, NTOK / 128);   // (8, 64)
    sgemm<<<gProj, 256>>>(q, Wpack,        QKV,        nullptr,
                          NTOK, Dd, Dd, Dd, QKV_LD, QKV_LD);
    sgemm<<<gProj, 256>>>(k, Wpack + 1024, QKV + 1024, nullptr,
                          NTOK, Dd, Dd, Dd, QKV_LD, QKV_LD);
    sgemm<<<gProj, 256>>>(v, Wpack + 2048, QKV + 2048, nullptr,
                          NTOK, Dd, Dd, Dd, QKV_LD, QKV_LD);

    const size_t attn_smem =
        (size_t)(HD * QT_LD + HD * QT_LD + AT_BN * VS_LD + AT_BM * QT_LD) * sizeof(float);
    cudaFuncSetAttribute(attn_kernel, cudaFuncAttributeMaxDynamicSharedMemorySize,
                         (int)attn_smem);
    attn_kernel<<<dim3(Ss / AT_BM, Bb * Hh), 256, attn_smem>>>(QKV, Obuf);

    dim3 gOut(Dd / 128, NTOK / 128);    // (8, 64)
    sgemm<<<gOut, 256>>>(Obuf, WoT, out, bo, NTOK, Dd, Dd, Dd, Dd, Dd);
}

// round 6
// speedup vs baseline: 1.6142x; 1.6142x over previous
#include <cuda_runtime.h>
#include <cuda_bf16.h>
#include <cstdint>

// Problem constants
#define Bb 4
#define Ss 2048
#define Dd 1024
#define Hh 16
#define HD 64
#define NTOK (Bb * Ss)          // 8192
#define QKV_LD 3072             // fused Q|K|V row stride

// ---------------- scratch (__device__ globals; no allocation allowed) ------
__device__ float g_Wt[3 * Dd * Dd];              // W^T packs: [n][k]
__device__ float g_QKV[(size_t)NTOK * QKV_LD];   // 96 MB
__device__ float g_Obuf[(size_t)NTOK * Dd];      // 32 MB

// ---------------- helpers ---------------------------------------------------
__device__ __forceinline__ uint32_t cvt_tf32(float f) {
    uint32_t u;
    asm("cvt.rna.tf32.f32 %0, %1;" : "=r"(u) : "f"(f));
    return u;
}

// mma.sync m16n8k8 tf32 (row.col), f32 accumulate
#define MMA_TF32(d, a, b)                                                   \
    asm volatile(                                                           \
        "mma.sync.aligned.m16n8k8.row.col.f32.tf32.tf32.f32 "               \
        "{%0,%1,%2,%3}, {%4,%5,%6,%7}, {%8,%9}, {%0,%1,%2,%3};"             \
        : "+f"((d)[0]), "+f"((d)[1]), "+f"((d)[2]), "+f"((d)[3])            \
        : "r"((a).x), "r"((a).y), "r"((a).z), "r"((a).w),                   \
          "r"((b).x), "r"((b).y))

// ---------------- weight pack: Wt[s][n][k] = W_s[h, k, j], n = h*64+j -------
__global__ void pack_weights(const float* __restrict__ Wq,
                             const float* __restrict__ Wk,
                             const float* __restrict__ Wv)
{
    const int total = 3 * Dd * Dd;
    for (int idx = blockIdx.x * blockDim.x + threadIdx.x; idx < total;
         idx += gridDim.x * blockDim.x) {
        int s = idx >> 20;
        int rem = idx & ((1 << 20) - 1);
        int n = rem >> 10;
        int k = rem & 1023;
        int h = n >> 6;
        int j = n & 63;
        const float* W = (s == 0) ? Wq : (s == 1) ? Wk : Wv;
        g_Wt[idx] = W[h * (Dd * HD) + k * HD + j];
    }
}

// ---------------- TF32 mma.sync GEMM ----------------------------------------
// C[M,N] = A[M,K] * B^T (+bias), B given as Bw[N][K] row-major. K = 1024.
// CTA tile 128x128, K-tile 32, 256 threads (8 warps; warp tile 64x32).
// SMEM holds fragment-native layouts:
//   As: [mt(8)][ks(4)][lane(32)][slot(4)]  (a0..a3 of m16n8k8)
//   Bs: [nt(16)][ks(4)][lane(32)][slot(2)] (b0..b1)
// with a ks-based XOR swizzle for conflict-free stage-in.

__device__ __forceinline__ void stsA(float* As, int row, int kc, float4 v) {
    const int mt = row >> 4;
    const int lnb = (row & 7) << 2;
    const int sr = (row >> 3) & 1;
    const float e[4] = {v.x, v.y, v.z, v.w};
#pragma unroll
    for (int j = 0; j < 4; ++j) {
        const int k = kc + j;
        const int ks = k >> 3;
        const int slot = sr | (((k >> 2) & 1) << 1);
        const int idx = (((mt << 2) | ks) << 7) |
                        ((((lnb | j) << 2) ^ (ks << 3))) | slot;
        As[idx] = __uint_as_float(cvt_tf32(e[j]));
    }
}

__device__ __forceinline__ void stsB(float* Bs, int n, int kc, float4 v) {
    const int nt = n >> 3;
    const int lnb = (n & 7) << 2;
    const float e[4] = {v.x, v.y, v.z, v.w};
#pragma unroll
    for (int j = 0; j < 4; ++j) {
        const int k = kc + j;
        const int ks = k >> 3;
        const int slot = (k >> 2) & 1;
        const int idx = (((nt << 2) | ks) << 6) |
                        ((((lnb | j) << 1) ^ (ks << 2))) | slot;
        Bs[idx] = __uint_as_float(cvt_tf32(e[j]));
    }
}

__global__ void __launch_bounds__(256)
gemm_mma(const float* __restrict__ A, const float* __restrict__ Bw,
         float* __restrict__ C, const float* __restrict__ bias,
         int lda, int ldc)
{
    extern __shared__ float smf[];
    // [buf][4096] each for A and B
    float* Asm = smf;            // 2 * 4096
    float* Bsm = smf + 8192;     // 2 * 4096

    const int tid = threadIdx.x;
    const int lane = tid & 31;
    const int w = tid >> 5;
    const int wm = w >> 2;        // 0..1
    const int wn = w & 3;         // 0..3
    const int bm = blockIdx.y * 128;
    const int bn = blockIdx.x * 128;

    float acc[4][4][4];
#pragma unroll
    for (int i = 0; i < 4; i++)
#pragma unroll
        for (int j = 0; j < 4; j++)
#pragma unroll
            for (int r = 0; r < 4; r++) acc[i][j][r] = 0.f;

    const float* Ab = A + (size_t)bm * lda;
    const float* Bb2 = Bw + (size_t)bn * 1024;

    // prologue: stage kt = 0 into buffer 0
    {
#pragma unroll
        for (int i = 0; i < 4; ++i) {
            const int f = tid + 256 * i;
            const int row = f >> 3;
            const int kc = (f & 7) << 2;
            float4 av = *(const float4*)(Ab + (size_t)row * lda + kc);
            float4 bv = *(const float4*)(Bb2 + (size_t)row * 1024 + kc);
            stsA(Asm, row, kc, av);
            stsB(Bsm, row, kc, bv);
        }
    }
    __syncthreads();

    for (int kt = 0; kt < 32; ++kt) {
        const bool more = (kt + 1) < 32;
        float4 ar[4], br[4];
        if (more) {
            const int koff = (kt + 1) * 32;
#pragma unroll
            for (int i = 0; i < 4; ++i) {
                const int f = tid + 256 * i;
                const int row = f >> 3;
                const int kc = (f & 7) << 2;
                ar[i] = *(const float4*)(Ab + (size_t)row * lda + koff + kc);
                br[i] = *(const float4*)(Bb2 + (size_t)row * 1024 + koff + kc);
            }
        }

        // compute on buffer kt&1
        const float* Ap = Asm + (kt & 1) * 4096;
        const float* Bp = Bsm + (kt & 1) * 4096;
#pragma unroll
        for (int ks = 0; ks < 4; ++ks) {
            uint4 af[4];
            uint2 bf[4];
#pragma unroll
            for (int mt = 0; mt < 4; ++mt) {
                const int mtg = wm * 4 + mt;
                af[mt] = *(const uint4*)&Ap[(((mtg << 2) | ks) << 7) |
                                            ((lane << 2) ^ (ks << 3))];
            }
#pragma unroll
            for (int nt = 0; nt < 4; ++nt) {
                const int ntg = wn * 4 + nt;
                bf[nt] = *(const uint2*)&Bp[(((ntg << 2) | ks) << 6) |
                                            ((lane << 1) ^ (ks << 2))];
            }
#pragma unroll
            for (int mt = 0; mt < 4; ++mt)
#pragma unroll
                for (int nt = 0; nt < 4; ++nt)
                    MMA_TF32(acc[mt][nt], af[mt], bf[nt]);
        }

        if (more) {
            float* An = Asm + ((kt + 1) & 1) * 4096;
            float* Bn = Bsm + ((kt + 1) & 1) * 4096;
#pragma unroll
            for (int i = 0; i < 4; ++i) {
                const int f = tid + 256 * i;
                const int row = f >> 3;
                const int kc = (f & 7) << 2;
                stsA(An, row, kc, ar[i]);
                stsB(Bn, row, kc, br[i]);
            }
        }
        __syncthreads();
    }

    // epilogue: c0=(g,2t) c1=(g,2t+1) c2=(g+8,2t) c3=(g+8,2t+1)
    const int g = lane >> 2;
    const int t2 = (lane & 3) << 1;
#pragma unroll
    for (int mt = 0; mt < 4; ++mt) {
        const int row = bm + wm * 64 + mt * 16 + g;
#pragma unroll
        for (int nt = 0; nt < 4; ++nt) {
            const int col = bn + wn * 32 + nt * 8 + t2;
            float b0 = 0.f, b1 = 0.f;
            if (bias) { b0 = bias[col]; b1 = bias[col + 1]; }
            float2 lo = make_float2(acc[mt][nt][0] + b0, acc[mt][nt][1] + b1);
            float2 hi = make_float2(acc[mt][nt][2] + b0, acc[mt][nt][3] + b1);
            *(float2*)&C[(size_t)row * ldc + col] = lo;
            *(float2*)&C[(size_t)(row + 8) * ldc + col] = hi;
        }
    }
}

// ---------------- flash attention (causal, fp32 SIMT — proven) -------------
#define AT_BM 128
#define AT_BN 128
#define QT_LD 132
#define VS_LD 68

__global__ __launch_bounds__(256, 1)
void attn_kernel(const float* __restrict__ QKV, float* __restrict__ O)
{
    extern __shared__ float smf[];
    float* Qt = smf;
    float* Kt = Qt + HD * QT_LD;
    float* Vs = Kt + HD * QT_LD;
    float* Ps = Vs + AT_BN * VS_LD;

    const int tid = threadIdx.x;
    const int tx = tid & 15;
    const int ty = tid >> 4;

    const int qt = (gridDim.x - 1) - blockIdx.x;   // heavy tiles first
    const int bh = blockIdx.y;
    const int b = bh / Hh;
    const int h = bh % Hh;

    const float scale = 0.125f;
    const int q0 = qt * AT_BM;

    {
        const float* Qg = QKV + ((size_t)(b * Ss + q0)) * QKV_LD + h * HD;
#pragma unroll
        for (int i = 0; i < 8; ++i) {
            int f = tid + i * 256;
            int r = f >> 4;
            int c4 = (f & 15) << 2;
            float4 v = *(const float4*)(Qg + (size_t)r * QKV_LD + c4);
            Qt[(c4 + 0) * QT_LD + r] = v.x;
            Qt[(c4 + 1) * QT_LD + r] = v.y;
            Qt[(c4 + 2) * QT_LD + r] = v.z;
            Qt[(c4 + 3) * QT_LD + r] = v.w;
        }
    }

    float m[8], l[8], acc[8][4];
#pragma unroll
    for (int r = 0; r < 8; r++) {
        m[r] = -1e30f; l[r] = 0.f;
#pragma unroll
        for (int c = 0; c < 4; c++) acc[r][c] = 0.f;
    }

    const int row_base = ty * 8;

    for (int jt = 0; jt <= qt; ++jt) {
        const int k0 = jt * AT_BN;
        const float* Kg = QKV + ((size_t)(b * Ss + k0)) * QKV_LD + 1024 + h * HD;
        const float* Vg = QKV + ((size_t)(b * Ss + k0)) * QKV_LD + 2048 + h * HD;

        __syncthreads();
#pragma unroll
        for (int i = 0; i < 8; ++i) {
            int f = tid + i * 256;
            int r = f >> 4;
            int c4 = (f & 15) << 2;
            float4 kv = *(const float4*)(Kg + (size_t)r * QKV_LD + c4);
            Kt[(c4 + 0) * QT_LD + r] = kv.x;
            Kt[(c4 + 1) * QT_LD + r] = kv.y;
            Kt[(c4 + 2) * QT_LD + r] = kv.z;
            Kt[(c4 + 3) * QT_LD + r] = kv.w;
            float4 vv = *(const float4*)(Vg + (size_t)r * QKV_LD + c4);
            *(float4*)&Vs[r * VS_LD + c4] = vv;
        }
        __syncthreads();

        float s[8][8];
#pragma unroll
        for (int i = 0; i < 8; i++)
#pragma unroll
            for (int j = 0; j < 8; j++) s[i][j] = 0.f;
#pragma unroll
        for (int kk = 0; kk < HD; ++kk) {
            float a[8], bb2[8];
            *(float4*)&a[0] = *(const float4*)&Qt[kk * QT_LD + row_base];
            *(float4*)&a[4] = *(const float4*)&Qt[kk * QT_LD + row_base + 4];
            *(float4*)&bb2[0] = *(const float4*)&Kt[kk * QT_LD + tx * 8];
            *(float4*)&bb2[4] = *(const float4*)&Kt[kk * QT_LD + tx * 8 + 4];
#pragma unroll
            for (int i = 0; i < 8; i++)
#pragma unroll
                for (int j = 0; j < 8; j++) s[i][j] += a[i] * bb2[j];
        }

        const bool diag = (jt == qt);
#pragma unroll
        for (int r = 0; r < 8; r++) {
            const int qrow = q0 + row_base + r;
            float mx = -1e30f;
#pragma unroll
            for (int c = 0; c < 8; c++) {
                float sv = s[r][c] * scale;
                if (diag && (k0 + tx * 8 + c > qrow)) sv = -1e30f;
                s[r][c] = sv;
                mx = fmaxf(mx, sv);
            }
#pragma unroll
            for (int off = 1; off < 16; off <<= 1)
                mx = fmaxf(mx, __shfl_xor_sync(0xffffffffu, mx, off));
            const float mnew = fmaxf(m[r], mx);
            float sum = 0.f;
#pragma unroll
            for (int c = 0; c < 8; c++) {
                float p = __expf(s[r][c] - mnew);
                s[r][c] = p;
                sum += p;
            }
#pragma unroll
            for (int off = 1; off < 16; off <<= 1)
                sum += __shfl_xor_sync(0xffffffffu, sum, off);
            const float alpha = __expf(m[r] - mnew);
            l[r] = l[r] * alpha + sum;
            m[r] = mnew;
#pragma unroll
            for (int c = 0; c < 4; c++) acc[r][c] *= alpha;
            *(float4*)&Ps[(row_base + r) * QT_LD + tx * 8] =
                make_float4(s[r][0], s[r][1], s[r][2], s[r][3]);
            *(float4*)&Ps[(row_base + r) * QT_LD + tx * 8 + 4] =
                make_float4(s[r][4], s[r][5], s[r][6], s[r][7]);
        }
        __syncthreads();

#pragma unroll 4
        for (int kc = 0; kc < AT_BN; ++kc) {
            float4 vv = *(const float4*)&Vs[kc * VS_LD + tx * 4];
#pragma unroll
            for (int r = 0; r < 8; r++) {
                float p = Ps[(row_base + r) * QT_LD + kc];
                acc[r][0] += p * vv.x;
                acc[r][1] += p * vv.y;
                acc[r][2] += p * vv.z;
                acc[r][3] += p * vv.w;
            }
        }
    }

#pragma unroll
    for (int r = 0; r < 8; r++) {
        const float inv = 1.f / l[r];
        float4 o = make_float4(acc[r][0] * inv, acc[r][1] * inv,
                               acc[r][2] * inv, acc[r][3] * inv);
        *(float4*)&O[((size_t)(b * Ss + q0 + row_base + r)) * Dd + h * HD + tx * 4] = o;
    }
}

// ---------------- launch ----------------------------------------------------
extern "C" void kernel_launch(void* const* d_in, const int* in_sizes, int n_in,
                              void* d_out, int out_size)
{
    (void)in_sizes; (void)n_in; (void)out_size;
    const float* q  = (const float*)d_in[0];
    const float* k  = (const float*)d_in[1];
    const float* v  = (const float*)d_in[2];
    const float* Wq = (const float*)d_in[3];
    const float* Wk = (const float*)d_in[4];
    const float* Wv = (const float*)d_in[5];
    const float* Wo = (const float*)d_in[6];
    const float* bo = (const float*)d_in[7];
    float* out = (float*)d_out;

    float *Wt, *QKV, *Obuf;
    cudaGetSymbolAddress((void**)&Wt, g_Wt);
    cudaGetSymbolAddress((void**)&QKV, g_QKV);
    cudaGetSymbolAddress((void**)&Obuf, g_Obuf);

    pack_weights<<<512, 256>>>(Wq, Wk, Wv);

    const int gemm_smem = 16384 * sizeof(float);   // 64 KB
    cudaFuncSetAttribute(gemm_mma, cudaFuncAttributeMaxDynamicSharedMemorySize,
                         gemm_smem);

    dim3 gProj(Dd / 128, NTOK / 128);   // (8, 64)
    gemm_mma<<<gProj, 256, gemm_smem>>>(q, Wt,               QKV,        nullptr, Dd, QKV_LD);
    gemm_mma<<<gProj, 256, gemm_smem>>>(k, Wt + 1024 * 1024, QKV + 1024, nullptr, Dd, QKV_LD);
    gemm_mma<<<gProj, 256, gemm_smem>>>(v, Wt + 2048 * 1024, QKV + 2048, nullptr, Dd, QKV_LD);

    const size_t attn_smem =
        (size_t)(HD * QT_LD + HD * QT_LD + AT_BN * VS_LD + AT_BM * QT_LD) * sizeof(float);
    cudaFuncSetAttribute(attn_kernel, cudaFuncAttributeMaxDynamicSharedMemorySize,
                         (int)attn_smem);
    attn_kernel<<<dim3(Ss / AT_BM, Bb * Hh), 256, attn_smem>>>(QKV, Obuf);

    // out = Obuf @ Wo^T + bo : Wo[n][k] row-major is already B^T layout
    gemm_mma<<<gProj, 256, gemm_smem>>>(Obuf, Wo, out, bo, Dd, Dd);
}

// round 12
// speedup vs baseline: 2.6541x; 1.6443x over previous
#include <cuda_runtime.h>
#include <cuda_bf16.h>
#include <cstdint>

// Problem constants
#define Bb 4
#define Ss 2048
#define Dd 1024
#define Hh 16
#define HD 64
#define NTOK (Bb * Ss)          // 8192
#define QKV_LD 3072             // fused Q|K|V row stride

// ---------------- scratch (__device__ globals; no allocation allowed) ------
__device__ float g_Wt[3 * Dd * Dd];              // W^T packs: [n][k]
__device__ float g_QKV[(size_t)NTOK * QKV_LD];   // 96 MB
__device__ float g_Obuf[(size_t)NTOK * Dd];      // 32 MB

// ---------------- helpers ---------------------------------------------------
__device__ __forceinline__ uint32_t cvt_tf32(float f) {
    uint32_t u;
    asm("cvt.rna.tf32.f32 %0, %1;" : "=r"(u) : "f"(f));
    return u;
}

// mma.sync m16n8k8 tf32 (row.col), f32 accumulate — acc as float array
#define MMA_TF32(d, a, b)                                                   \
    asm volatile(                                                           \
        "mma.sync.aligned.m16n8k8.row.col.f32.tf32.tf32.f32 "               \
        "{%0,%1,%2,%3}, {%4,%5,%6,%7}, {%8,%9}, {%0,%1,%2,%3};"             \
        : "+f"((d)[0]), "+f"((d)[1]), "+f"((d)[2]), "+f"((d)[3])            \
        : "r"((a).x), "r"((a).y), "r"((a).z), "r"((a).w),                   \
          "r"((b).x), "r"((b).y))

// same but acc is float4
#define MMA_TF32V(d, a, b)                                                  \
    asm volatile(                                                           \
        "mma.sync.aligned.m16n8k8.row.col.f32.tf32.tf32.f32 "               \
        "{%0,%1,%2,%3}, {%4,%5,%6,%7}, {%8,%9}, {%0,%1,%2,%3};"             \
        : "+f"((d).x), "+f"((d).y), "+f"((d).z), "+f"((d).w)                \
        : "r"((a).x), "r"((a).y), "r"((a).z), "r"((a).w),                   \
          "r"((b).x), "r"((b).y))

// ---------------- weight pack: Wt[s][n][k] = W_s[h, k, j], n = h*64+j -------
__global__ void pack_weights(const float* __restrict__ Wq,
                             const float* __restrict__ Wk,
                             const float* __restrict__ Wv)
{
    const int total = 3 * Dd * Dd;
    for (int idx = blockIdx.x * blockDim.x + threadIdx.x; idx < total;
         idx += gridDim.x * blockDim.x) {
        int s = idx >> 20;
        int rem = idx & ((1 << 20) - 1);
        int n = rem >> 10;
        int k = rem & 1023;
        int h = n >> 6;
        int j = n & 63;
        const float* W = (s == 0) ? Wq : (s == 1) ? Wk : Wv;
        g_Wt[idx] = W[h * (Dd * HD) + k * HD + j];
    }
}

// ---------------- TF32 mma.sync GEMM (R6-proven) ----------------------------
__device__ __forceinline__ void stsA(float* As, int row, int kc, float4 v) {
    const int mt = row >> 4;
    const int lnb = (row & 7) << 2;
    const int sr = (row >> 3) & 1;
    const float e[4] = {v.x, v.y, v.z, v.w};
#pragma unroll
    for (int j = 0; j < 4; ++j) {
        const int k = kc + j;
        const int ks = k >> 3;
        const int slot = sr | (((k >> 2) & 1) << 1);
        const int idx = (((mt << 2) | ks) << 7) |
                        ((((lnb | j) << 2) ^ (ks << 3))) | slot;
        As[idx] = __uint_as_float(cvt_tf32(e[j]));
    }
}

__device__ __forceinline__ void stsB(float* Bs, int n, int kc, float4 v) {
    const int nt = n >> 3;
    const int lnb = (n & 7) << 2;
    const float e[4] = {v.x, v.y, v.z, v.w};
#pragma unroll
    for (int j = 0; j < 4; ++j) {
        const int k = kc + j;
        const int ks = k >> 3;
        const int slot = (k >> 2) & 1;
        const int idx = (((nt << 2) | ks) << 6) |
                        ((((lnb | j) << 1) ^ (ks << 2))) | slot;
        Bs[idx] = __uint_as_float(cvt_tf32(e[j]));
    }
}

__global__ void __launch_bounds__(256)
gemm_mma(const float* __restrict__ A, const float* __restrict__ Bw,
         float* __restrict__ C, const float* __restrict__ bias,
         int lda, int ldc, int round_out)
{
    extern __shared__ float smf[];
    float* Asm = smf;            // 2 * 4096
    float* Bsm = smf + 8192;     // 2 * 4096

    const int tid = threadIdx.x;
    const int lane = tid & 31;
    const int w = tid >> 5;
    const int wm = w >> 2;
    const int wn = w & 3;
    const int bm = blockIdx.y * 128;
    const int bn = blockIdx.x * 128;

    float acc[4][4][4];
#pragma unroll
    for (int i = 0; i < 4; i++)
#pragma unroll
        for (int j = 0; j < 4; j++)
#pragma unroll
            for (int r = 0; r < 4; r++) acc[i][j][r] = 0.f;

    const float* Ab = A + (size_t)bm * lda;
    const float* Bb2 = Bw + (size_t)bn * 1024;

    {
#pragma unroll
        for (int i = 0; i < 4; ++i) {
            const int f = tid + 256 * i;
            const int row = f >> 3;
            const int kc = (f & 7) << 2;
            float4 av = *(const float4*)(Ab + (size_t)row * lda + kc);
            float4 bv = *(const float4*)(Bb2 + (size_t)row * 1024 + kc);
            stsA(Asm, row, kc, av);
            stsB(Bsm, row, kc, bv);
        }
    }
    __syncthreads();

    for (int kt = 0; kt < 32; ++kt) {
        const bool more = (kt + 1) < 32;
        float4 ar[4], br[4];
        if (more) {
            const int koff = (kt + 1) * 32;
#pragma unroll
            for (int i = 0; i < 4; ++i) {
                const int f = tid + 256 * i;
                const int row = f >> 3;
                const int kc = (f & 7) << 2;
                ar[i] = *(const float4*)(Ab + (size_t)row * lda + koff + kc);
                br[i] = *(const float4*)(Bb2 + (size_t)row * 1024 + koff + kc);
            }
        }

        const float* Ap = Asm + (kt & 1) * 4096;
        const float* Bp = Bsm + (kt & 1) * 4096;
#pragma unroll
        for (int ks = 0; ks < 4; ++ks) {
            uint4 af[4];
            uint2 bf[4];
#pragma unroll
            for (int mt = 0; mt < 4; ++mt) {
                const int mtg = wm * 4 + mt;
                af[mt] = *(const uint4*)&Ap[(((mtg << 2) | ks) << 7) |
                                            ((lane << 2) ^ (ks << 3))];
            }
#pragma unroll
            for (int nt = 0; nt < 4; ++nt) {
                const int ntg = wn * 4 + nt;
                bf[nt] = *(const uint2*)&Bp[(((ntg << 2) | ks) << 6) |
                                            ((lane << 1) ^ (ks << 2))];
            }
#pragma unroll
            for (int mt = 0; mt < 4; ++mt)
#pragma unroll
                for (int nt = 0; nt < 4; ++nt)
                    MMA_TF32(acc[mt][nt], af[mt], bf[nt]);
        }

        if (more) {
            float* An = Asm + ((kt + 1) & 1) * 4096;
            float* Bn = Bsm + ((kt + 1) & 1) * 4096;
#pragma unroll
            for (int i = 0; i < 4; ++i) {
                const int f = tid + 256 * i;
                const int row = f >> 3;
                const int kc = (f & 7) << 2;
                stsA(An, row, kc, ar[i]);
                stsB(Bn, row, kc, br[i]);
            }
        }
        __syncthreads();
    }

    const int g = lane >> 2;
    const int t2 = (lane & 3) << 1;
#pragma unroll
    for (int mt = 0; mt < 4; ++mt) {
        const int row = bm + wm * 64 + mt * 16 + g;
#pragma unroll
        for (int nt = 0; nt < 4; ++nt) {
            const int col = bn + wn * 32 + nt * 8 + t2;
            float b0 = 0.f, b1 = 0.f;
            if (bias) { b0 = bias[col]; b1 = bias[col + 1]; }
            float v0 = acc[mt][nt][0] + b0, v1 = acc[mt][nt][1] + b1;
            float v2 = acc[mt][nt][2] + b0, v3 = acc[mt][nt][3] + b1;
            if (round_out) {
                v0 = __uint_as_float(cvt_tf32(v0));
                v1 = __uint_as_float(cvt_tf32(v1));
                v2 = __uint_as_float(cvt_tf32(v2));
                v3 = __uint_as_float(cvt_tf32(v3));
            }
            *(float2*)&C[(size_t)row * ldc + col] = make_float2(v0, v1);
            *(float2*)&C[(size_t)(row + 8) * ldc + col] = make_float2(v2, v3);
        }
    }
}

// ---------------- flash attention: mma.sync tf32, register-staged K/V ------
// grid (16, 64), 256 threads / 8 warps. CTA: 128 q-rows, one (b,h).
// Smem: Ks[128][68], Vs[128][72], Ps[128][132]  (P tile is 128 COLS wide!)
#define KS_LD 68
#define VS_LD2 72
#define PS_LD 132
#define ATT_SMEM ((128 * KS_LD + 128 * VS_LD2 + 128 * PS_LD) * 4)

__global__ void __launch_bounds__(256, 1)
attn_mma(const float* __restrict__ QKV, float* __restrict__ O)
{
    extern __shared__ float smf[];
    float* Ks = smf;                       // [128][68]
    float* Vs = smf + 128 * KS_LD;         // [128][72]
    float* Ps = Vs + 128 * VS_LD2;         // [128][132]

    const int tid = threadIdx.x;
    const int lane = tid & 31;
    const int w = tid >> 5;
    const int g = lane >> 2;       // row group
    const int qd = lane & 3;       // quad col

    const int qt = (gridDim.x - 1) - (int)blockIdx.x;   // heavy tiles first
    const int bh = blockIdx.y;
    const int b = bh >> 4, h = bh & 15;
    const int q0 = qt * 128;

    const float* Qg = QKV + ((size_t)(b * Ss + q0)) * QKV_LD + h * HD;
    const float* Kg = QKV + ((size_t)b * Ss) * QKV_LD + 1024 + h * HD;
    const float* Vg = QKV + ((size_t)b * Ss) * QKV_LD + 2048 + h * HD;

    // per-thread tile load map: i=0..7, f = tid + i*256, r = f>>4, c4 = (f&15)<<2
    float4 kr[8], vr[8];

    // prologue: K(0) into regs, stage Q (scaled by 1/8, exact)
#pragma unroll
    for (int i = 0; i < 8; ++i) {
        int f = tid + i * 256, r = f >> 4, c4 = (f & 15) << 2;
        kr[i] = *(const float4*)(Kg + (size_t)r * QKV_LD + c4);
    }
#pragma unroll
    for (int i = 0; i < 8; ++i) {
        int f = tid + i * 256, r = f >> 4, c4 = (f & 15) << 2;
        float4 v = *(const float4*)(Qg + (size_t)r * QKV_LD + c4);
        v.x *= 0.125f; v.y *= 0.125f; v.z *= 0.125f; v.w *= 0.125f;
        *(float4*)&Ps[r * PS_LD + c4] = v;
    }
    __syncthreads();

    const int r0l = w * 16 + g;       // warp-local row (global row q0 + r0l)
    const int r1l = r0l + 8;

    uint4 qf[8];
#pragma unroll
    for (int kd = 0; kd < 8; ++kd) {
        const int base = r0l * PS_LD + kd * 8 + qd;
        qf[kd].x = __float_as_uint(Ps[base]);
        qf[kd].y = __float_as_uint(Ps[base + 8 * PS_LD]);
        qf[kd].z = __float_as_uint(Ps[base + 4]);
        qf[kd].w = __float_as_uint(Ps[base + 8 * PS_LD + 4]);
    }

    // store K(0) to smem; load V(0) to regs
#pragma unroll
    for (int i = 0; i < 8; ++i) {
        int f = tid + i * 256, r = f >> 4, c4 = (f & 15) << 2;
        *(float4*)&Ks[r * KS_LD + c4] = kr[i];
    }
#pragma unroll
    for (int i = 0; i < 8; ++i) {
        int f = tid + i * 256, r = f >> 4, c4 = (f & 15) << 2;
        vr[i] = *(const float4*)(Vg + (size_t)r * QKV_LD + c4);
    }
    __syncthreads();

    float m0 = -1e30f, m1 = -1e30f, l0 = 0.f, l1 = 0.f;
    float4 o[8];
#pragma unroll
    for (int nt = 0; nt < 8; ++nt) o[nt] = make_float4(0.f, 0.f, 0.f, 0.f);

    for (int jt = 0; jt <= qt; ++jt) {
        // invariant: Ks = K(jt) in smem, vr = V(jt) in regs, prev PV done
        const bool more = (jt < qt);

        // stage V(jt) to smem; issue K(jt+1) loads (hide under S-compute)
#pragma unroll
        for (int i = 0; i < 8; ++i) {
            int f = tid + i * 256, r = f >> 4, c4 = (f & 15) << 2;
            *(float4*)&Vs[r * VS_LD2 + c4] = vr[i];
        }
        if (more) {
            const float* Kt = Kg + (size_t)(jt + 1) * 128 * QKV_LD;
#pragma unroll
            for (int i = 0; i < 8; ++i) {
                int f = tid + i * 256, r = f >> 4, c4 = (f & 15) << 2;
                kr[i] = *(const float4*)(Kt + (size_t)r * QKV_LD + c4);
            }
        }

        // ---- S = (Q/8) K^T : 16 n-tiles x 8 k-tiles ----
        float4 s[16];
#pragma unroll
        for (int nt = 0; nt < 16; ++nt) {
            float4 a4 = make_float4(0.f, 0.f, 0.f, 0.f);
#pragma unroll
            for (int kd = 0; kd < 8; ++kd) {
                uint2 bf;
                const int kbase = (nt * 8 + g) * KS_LD + kd * 8 + qd;
                bf.x = __float_as_uint(Ks[kbase]);
                bf.y = __float_as_uint(Ks[kbase + 4]);
                MMA_TF32V(a4, qf[kd], bf);
            }
            s[nt] = a4;
        }

        // ---- mask + row max ----
        const bool diag = (jt == qt);
        float mx0 = -1e30f, mx1 = -1e30f;
#pragma unroll
        for (int nt = 0; nt < 16; ++nt) {
            if (diag) {
                const int c0 = nt * 8 + 2 * qd;
                if (c0 > r0l)     s[nt].x = -1e30f;
                if (c0 + 1 > r0l) s[nt].y = -1e30f;
                if (c0 > r1l)     s[nt].z = -1e30f;
                if (c0 + 1 > r1l) s[nt].w = -1e30f;
            }
            mx0 = fmaxf(mx0, fmaxf(s[nt].x, s[nt].y));
            mx1 = fmaxf(mx1, fmaxf(s[nt].z, s[nt].w));
        }
        mx0 = fmaxf(mx0, __shfl_xor_sync(0xffffffffu, mx0, 1));
        mx0 = fmaxf(mx0, __shfl_xor_sync(0xffffffffu, mx0, 2));
        mx1 = fmaxf(mx1, __shfl_xor_sync(0xffffffffu, mx1, 1));
        mx1 = fmaxf(mx1, __shfl_xor_sync(0xffffffffu, mx1, 2));

        const float mn0 = fmaxf(m0, mx0), mn1 = fmaxf(m1, mx1);
        const float a0 = __expf(m0 - mn0), a1 = __expf(m1 - mn1);
        float sum0 = 0.f, sum1 = 0.f;

        __syncwarp();    // prior PV reads of this warp's Ps stripe done
#pragma unroll
        for (int nt = 0; nt < 16; ++nt) {
            const float px = __expf(s[nt].x - mn0);
            const float py = __expf(s[nt].y - mn0);
            const float pz = __expf(s[nt].z - mn1);
            const float pw = __expf(s[nt].w - mn1);
            sum0 += px + py;
            sum1 += pz + pw;
            const int cb = nt * 8 + 2 * qd;
            *(float2*)&Ps[r0l * PS_LD + cb] = make_float2(
                __uint_as_float(cvt_tf32(px)), __uint_as_float(cvt_tf32(py)));
            *(float2*)&Ps[r1l * PS_LD + cb] = make_float2(
                __uint_as_float(cvt_tf32(pz)), __uint_as_float(cvt_tf32(pw)));
        }
        sum0 += __shfl_xor_sync(0xffffffffu, sum0, 1);
        sum0 += __shfl_xor_sync(0xffffffffu, sum0, 2);
        sum1 += __shfl_xor_sync(0xffffffffu, sum1, 1);
        sum1 += __shfl_xor_sync(0xffffffffu, sum1, 2);
        l0 = l0 * a0 + sum0; m0 = mn0;
        l1 = l1 * a1 + sum1; m1 = mn1;

#pragma unroll
        for (int nt = 0; nt < 8; ++nt) {
            o[nt].x *= a0; o[nt].y *= a0;
            o[nt].z *= a1; o[nt].w *= a1;
        }
        __syncwarp();    // P visible to all lanes of this warp

        __syncthreads(); // Vs staged by all; S-compute done reading Ks

        // stage K(jt+1) to smem; issue V(jt+1) loads (hide under PV)
        if (more) {
#pragma unroll
            for (int i = 0; i < 8; ++i) {
                int f = tid + i * 256, r = f >> 4, c4 = (f & 15) << 2;
                *(float4*)&Ks[r * KS_LD + c4] = kr[i];
            }
            const float* Vt = Vg + (size_t)(jt + 1) * 128 * QKV_LD;
#pragma unroll
            for (int i = 0; i < 8; ++i) {
                int f = tid + i * 256, r = f >> 4, c4 = (f & 15) << 2;
                vr[i] = *(const float4*)(Vt + (size_t)r * QKV_LD + c4);
            }
        }

        // ---- O += P V : 16 k-tiles x 8 n-tiles ----
#pragma unroll
        for (int kt2 = 0; kt2 < 16; ++kt2) {
            uint4 af;
            const int pbase = r0l * PS_LD + kt2 * 8 + qd;
            af.x = __float_as_uint(Ps[pbase]);
            af.y = __float_as_uint(Ps[pbase + 8 * PS_LD]);
            af.z = __float_as_uint(Ps[pbase + 4]);
            af.w = __float_as_uint(Ps[pbase + 8 * PS_LD + 4]);
#pragma unroll
            for (int nt = 0; nt < 8; ++nt) {
                uint2 bf;
                const int vbase = (kt2 * 8 + qd) * VS_LD2 + nt * 8 + g;
                bf.x = __float_as_uint(Vs[vbase]);
                bf.y = __float_as_uint(Vs[vbase + 4 * VS_LD2]);
                MMA_TF32V(o[nt], af, bf);
            }
        }

        __syncthreads(); // PV done reading Vs; Ks(jt+1) staged for next iter
    }

    // epilogue
    const float i0 = 1.f / l0, i1 = 1.f / l1;
    float* Or0 = O + ((size_t)(b * Ss + q0 + r0l)) * Dd + h * HD;
    float* Or1 = Or0 + (size_t)8 * Dd;
#pragma unroll
    for (int nt = 0; nt < 8; ++nt) {
        const int cb = nt * 8 + 2 * qd;
        *(float2*)&Or0[cb] = make_float2(o[nt].x * i0, o[nt].y * i0);
        *(float2*)&Or1[cb] = make_float2(o[nt].z * i1, o[nt].w * i1);
    }
}

// ---------------- launch ----------------------------------------------------
extern "C" void kernel_launch(void* const* d_in, const int* in_sizes, int n_in,
                              void* d_out, int out_size)
{
    (void)in_sizes; (void)n_in; (void)out_size;
    const float* q  = (const float*)d_in[0];
    const float* k  = (const float*)d_in[1];
    const float* v  = (const float*)d_in[2];
    const float* Wq = (const float*)d_in[3];
    const float* Wk = (const float*)d_in[4];
    const float* Wv = (const float*)d_in[5];
    const float* Wo = (const float*)d_in[6];
    const float* bo = (const float*)d_in[7];
    float* out = (float*)d_out;

    float *Wt, *QKV, *Obuf;
    cudaGetSymbolAddress((void**)&Wt, g_Wt);
    cudaGetSymbolAddress((void**)&QKV, g_QKV);
    cudaGetSymbolAddress((void**)&Obuf, g_Obuf);

    pack_weights<<<512, 256>>>(Wq, Wk, Wv);

    const int gemm_smem = 16384 * sizeof(float);   // 64 KB
    cudaFuncSetAttribute(gemm_mma, cudaFuncAttributeMaxDynamicSharedMemorySize,
                         gemm_smem);

    dim3 gProj(Dd / 128, NTOK / 128);   // (8, 64)
    // QKV projections: outputs pre-rounded to tf32 for the attention stage
    gemm_mma<<<gProj, 256, gemm_smem>>>(q, Wt,               QKV,        nullptr, Dd, QKV_LD, 1);
    gemm_mma<<<gProj, 256, gemm_smem>>>(k, Wt + 1024 * 1024, QKV + 1024, nullptr, Dd, QKV_LD, 1);
    gemm_mma<<<gProj, 256, gemm_smem>>>(v, Wt + 2048 * 1024, QKV + 2048, nullptr, Dd, QKV_LD, 1);

    cudaFuncSetAttribute(attn_mma, cudaFuncAttributeMaxDynamicSharedMemorySize,
                         ATT_SMEM);
    attn_mma<<<dim3(Ss / 128, Bb * Hh), 256, ATT_SMEM>>>(QKV, Obuf);

    // out = Obuf @ Wo^T + bo : Wo[n][k] row-major is already B^T layout
    gemm_mma<<<gProj, 256, gemm_smem>>>(Obuf, Wo, out, bo, Dd, Dd, 0);
}

// round 13
// speedup vs baseline: 2.7816x; 1.0480x over previous
#include <cuda_runtime.h>
#include <cuda_bf16.h>
#include <cstdint>

// Problem constants
#define Bb 4
#define Ss 2048
#define Dd 1024
#define Hh 16
#define HD 64
#define NTOK (Bb * Ss)          // 8192
#define QKV_LD 3072             // fused Q|K|V row stride

// ---------------- scratch (__device__ globals; no allocation allowed) ------
__device__ float g_Wt[3 * Dd * Dd];              // W^T packs (tf32): [n][k]
__device__ float g_WoR[Dd * Dd];                 // Wo rounded (tf32): [n][k]
__device__ float g_Ain[(size_t)3 * NTOK * Dd];   // q|k|v rounded (tf32), 96 MB
__device__ float g_QKV[(size_t)NTOK * QKV_LD];   // 96 MB
__device__ float g_Obuf[(size_t)NTOK * Dd];      // 32 MB

// ---------------- helpers ---------------------------------------------------
__device__ __forceinline__ uint32_t cvt_tf32(float f) {
    uint32_t u;
    asm("cvt.rna.tf32.f32 %0, %1;" : "=r"(u) : "f"(f));
    return u;
}
__device__ __forceinline__ float rtf(float f) {
    return __uint_as_float(cvt_tf32(f));
}

// mma.sync m16n8k8 tf32 (row.col), f32 accumulate — acc as float array
#define MMA_TF32(d, a, b)                                                   \
    asm volatile(                                                           \
        "mma.sync.aligned.m16n8k8.row.col.f32.tf32.tf32.f32 "               \
        "{%0,%1,%2,%3}, {%4,%5,%6,%7}, {%8,%9}, {%0,%1,%2,%3};"             \
        : "+f"((d)[0]), "+f"((d)[1]), "+f"((d)[2]), "+f"((d)[3])            \
        : "r"((a).x), "r"((a).y), "r"((a).z), "r"((a).w),                   \
          "r"((b).x), "r"((b).y))

// same but acc is float4
#define MMA_TF32V(d, a, b)                                                  \
    asm volatile(                                                           \
        "mma.sync.aligned.m16n8k8.row.col.f32.tf32.tf32.f32 "               \
        "{%0,%1,%2,%3}, {%4,%5,%6,%7}, {%8,%9}, {%0,%1,%2,%3};"             \
        : "+f"((d).x), "+f"((d).y), "+f"((d).z), "+f"((d).w)                \
        : "r"((a).x), "r"((a).y), "r"((a).z), "r"((a).w),                   \
          "r"((b).x), "r"((b).y))

// ---------------- pack + pre-round ------------------------------------------
// Wt[s][n][k] = tf32(W_s[h,k,j]), n=h*64+j ; WoR[n][k] = tf32(Wo[n][k]) ;
// Ain[s][t][k] = tf32({q,k,v}[t][k])
__global__ void pack_round(const float* __restrict__ q,
                           const float* __restrict__ k,
                           const float* __restrict__ v,
                           const float* __restrict__ Wq,
                           const float* __restrict__ Wk,
                           const float* __restrict__ Wv,
                           const float* __restrict__ Wo)
{
    const int T = blockDim.x * gridDim.x;
    const int t0 = blockIdx.x * blockDim.x + threadIdx.x;

    for (int idx = t0; idx < 3 * Dd * Dd; idx += T) {
        int s = idx >> 20;
        int rem = idx & ((1 << 20) - 1);
        int n = rem >> 10;
        int kk = rem & 1023;
        int h = n >> 6;
        int j = n & 63;
        const float* W = (s == 0) ? Wq : (s == 1) ? Wk : Wv;
        g_Wt[idx] = rtf(W[h * (Dd * HD) + kk * HD + j]);
    }
    for (int idx = t0; idx < Dd * Dd; idx += T)
        g_WoR[idx] = rtf(Wo[idx]);

    const int quart = (NTOK * Dd) >> 2;   // float4 count per section
    for (int idx = t0; idx < 3 * quart; idx += T) {
        int s = idx / quart;
        int rem = idx - s * quart;
        const float4* src = (const float4*)((s == 0) ? q : (s == 1) ? k : v);
        float4 val = src[rem];
        val.x = rtf(val.x); val.y = rtf(val.y);
        val.z = rtf(val.z); val.w = rtf(val.w);
        ((float4*)g_Ain)[(size_t)s * quart + rem] = val;
    }
}

// ---------------- TF32 mma.sync GEMM ----------------------------------------
// C[M,N] = A[M,K] * B^T (+bias), B[N][K] row-major, K=1024, inputs tf32-ready.
// CTA 128x128, K-tile 32, 256 threads (8 warps; warp tile 64x32).
// gridDim.z==3: z selects A section (NTOK*1024), B section (1024*1024),
//               C column offset (z*1024).
__device__ __forceinline__ void stsA(float* As, int row, int kc, float4 v) {
    const int mt = row >> 4;
    const int lnb = (row & 7) << 2;
    const int sr = (row >> 3) & 1;
    const float e[4] = {v.x, v.y, v.z, v.w};
#pragma unroll
    for (int j = 0; j < 4; ++j) {
        const int k = kc + j;
        const int ks = k >> 3;
        const int slot = sr | (((k >> 2) & 1) << 1);
        const int idx = (((mt << 2) | ks) << 7) |
                        ((((lnb | j) << 2) ^ (ks << 3))) | slot;
        As[idx] = e[j];
    }
}

__device__ __forceinline__ void stsB(float* Bs, int n, int kc, float4 v) {
    const int nt = n >> 3;
    const int lnb = (n & 7) << 2;
    const float e[4] = {v.x, v.y, v.z, v.w};
#pragma unroll
    for (int j = 0; j < 4; ++j) {
        const int k = kc + j;
        const int ks = k >> 3;
        const int slot = (k >> 2) & 1;
        const int idx = (((nt << 2) | ks) << 6) |
                        ((((lnb | j) << 1) ^ (ks << 2))) | slot;
        Bs[idx] = e[j];
    }
}

__global__ void __launch_bounds__(256)
gemm_mma(const float* __restrict__ A, const float* __restrict__ Bw,
         float* __restrict__ C, const float* __restrict__ bias,
         int lda, int ldc, int round_out)
{
    extern __shared__ float smf[];
    float* Asm = smf;            // 2 * 4096
    float* Bsm = smf + 8192;     // 2 * 4096

    const int tid = threadIdx.x;
    const int lane = tid & 31;
    const int w = tid >> 5;
    const int wm = w >> 2;
    const int wn = w & 3;
    const int bm = blockIdx.y * 128;
    const int bn = blockIdx.x * 128;

    if (gridDim.z == 3) {
        const int z = blockIdx.z;
        A  += (size_t)z * NTOK * Dd;
        Bw += (size_t)z * Dd * Dd;
        C  += (size_t)z * Dd;        // column offset within QKV_LD row
    }

    float acc[4][4][4];
#pragma unroll
    for (int i = 0; i < 4; i++)
#pragma unroll
        for (int j = 0; j < 4; j++)
#pragma unroll
            for (int r = 0; r < 4; r++) acc[i][j][r] = 0.f;

    const float* Ab = A + (size_t)bm * lda;
    const float* Bb2 = Bw + (size_t)bn * 1024;

    {
#pragma unroll
        for (int i = 0; i < 4; ++i) {
            const int f = tid + 256 * i;
            const int row = f >> 3;
            const int kc = (f & 7) << 2;
            float4 av = *(const float4*)(Ab + (size_t)row * lda + kc);
            float4 bv = *(const float4*)(Bb2 + (size_t)row * 1024 + kc);
            stsA(Asm, row, kc, av);
            stsB(Bsm, row, kc, bv);
        }
    }
    __syncthreads();

    for (int kt = 0; kt < 32; ++kt) {
        const bool more = (kt + 1) < 32;
        float4 ar[4], br[4];
        if (more) {
            const int koff = (kt + 1) * 32;
#pragma unroll
            for (int i = 0; i < 4; ++i) {
                const int f = tid + 256 * i;
                const int row = f >> 3;
                const int kc = (f & 7) << 2;
                ar[i] = *(const float4*)(Ab + (size_t)row * lda + koff + kc);
                br[i] = *(const float4*)(Bb2 + (size_t)row * 1024 + koff + kc);
            }
        }

        const float* Ap = Asm + (kt & 1) * 4096;
        const float* Bp = Bsm + (kt & 1) * 4096;

        // software-pipelined fragment loads (double-buffered over ks)
        uint4 af[2][4];
        uint2 bf[2][4];
#pragma unroll
        for (int mt = 0; mt < 4; ++mt) {
            const int mtg = wm * 4 + mt;
            af[0][mt] = *(const uint4*)&Ap[((mtg << 2) << 7) | (lane << 2)];
        }
#pragma unroll
        for (int nt = 0; nt < 4; ++nt) {
            const int ntg = wn * 4 + nt;
            bf[0][nt] = *(const uint2*)&Bp[((ntg << 2) << 6) | (lane << 1)];
        }
#pragma unroll
        for (int ks = 0; ks < 4; ++ks) {
            const int cur = ks & 1, nxt = cur ^ 1;
            if (ks < 3) {
                const int kn = ks + 1;
#pragma unroll
                for (int mt = 0; mt < 4; ++mt) {
                    const int mtg = wm * 4 + mt;
                    af[nxt][mt] = *(const uint4*)&Ap[(((mtg << 2) | kn) << 7) |
                                                     ((lane << 2) ^ (kn << 3))];
                }
#pragma unroll
                for (int nt = 0; nt < 4; ++nt) {
                    const int ntg = wn * 4 + nt;
                    bf[nxt][nt] = *(const uint2*)&Bp[(((ntg << 2) | kn) << 6) |
                                                     ((lane << 1) ^ (kn << 2))];
                }
            }
#pragma unroll
            for (int mt = 0; mt < 4; ++mt)
#pragma unroll
                for (int nt = 0; nt < 4; ++nt)
                    MMA_TF32(acc[mt][nt], af[cur][mt], bf[cur][nt]);
        }

        if (more) {
            float* An = Asm + ((kt + 1) & 1) * 4096;
            float* Bn = Bsm + ((kt + 1) & 1) * 4096;
#pragma unroll
            for (int i = 0; i < 4; ++i) {
                const int f = tid + 256 * i;
                const int row = f >> 3;
                const int kc = (f & 7) << 2;
                stsA(An, row, kc, ar[i]);
                stsB(Bn, row, kc, br[i]);
            }
        }
        __syncthreads();
    }

    const int g = lane >> 2;
    const int t2 = (lane & 3) << 1;
#pragma unroll
    for (int mt = 0; mt < 4; ++mt) {
        const int row = bm + wm * 64 + mt * 16 + g;
#pragma unroll
        for (int nt = 0; nt < 4; ++nt) {
            const int col = bn + wn * 32 + nt * 8 + t2;
            float b0 = 0.f, b1 = 0.f;
            if (bias) { b0 = bias[col]; b1 = bias[col + 1]; }
            float v0 = acc[mt][nt][0] + b0, v1 = acc[mt][nt][1] + b1;
            float v2 = acc[mt][nt][2] + b0, v3 = acc[mt][nt][3] + b1;
            if (round_out) {
                v0 = rtf(v0); v1 = rtf(v1); v2 = rtf(v2); v3 = rtf(v3);
            }
            *(float2*)&C[(size_t)row * ldc + col] = make_float2(v0, v1);
            *(float2*)&C[(size_t)(row + 8) * ldc + col] = make_float2(v2, v3);
        }
    }
}

// ---------------- flash attention: mma.sync tf32, register-staged K/V ------
// grid (16, 64), 256 threads / 8 warps. CTA: 128 q-rows, one (b,h).
// Smem: Ks[128][68], Vs[128][72], Ps[128][132]
#define KS_LD 68
#define VS_LD2 72
#define PS_LD 132
#define ATT_SMEM ((128 * KS_LD + 128 * VS_LD2 + 128 * PS_LD) * 4)

__global__ void __launch_bounds__(256, 1)
attn_mma(const float* __restrict__ QKV, float* __restrict__ O)
{
    extern __shared__ float smf[];
    float* Ks = smf;                       // [128][68]
    float* Vs = smf + 128 * KS_LD;         // [128][72]
    float* Ps = Vs + 128 * VS_LD2;         // [128][132]

    const int tid = threadIdx.x;
    const int lane = tid & 31;
    const int w = tid >> 5;
    const int g = lane >> 2;       // row group
    const int qd = lane & 3;       // quad col

    const int qt = (gridDim.x - 1) - (int)blockIdx.x;   // heavy tiles first
    const int bh = blockIdx.y;
    const int b = bh >> 4, h = bh & 15;
    const int q0 = qt * 128;

    const float* Qg = QKV + ((size_t)(b * Ss + q0)) * QKV_LD + h * HD;
    const float* Kg = QKV + ((size_t)b * Ss) * QKV_LD + 1024 + h * HD;
    const float* Vg = QKV + ((size_t)b * Ss) * QKV_LD + 2048 + h * HD;

    float4 kr[8], vr[8];

    // prologue: K(0) into regs, stage Q (scaled by 1/8, exact)
#pragma unroll
    for (int i = 0; i < 8; ++i) {
        int f = tid + i * 256, r = f >> 4, c4 = (f & 15) << 2;
        kr[i] = *(const float4*)(Kg + (size_t)r * QKV_LD + c4);
    }
#pragma unroll
    for (int i = 0; i < 8; ++i) {
        int f = tid + i * 256, r = f >> 4, c4 = (f & 15) << 2;
        float4 v = *(const float4*)(Qg + (size_t)r * QKV_LD + c4);
        v.x *= 0.125f; v.y *= 0.125f; v.z *= 0.125f; v.w *= 0.125f;
        *(float4*)&Ps[r * PS_LD + c4] = v;
    }
    __syncthreads();

    const int r0l = w * 16 + g;
    const int r1l = r0l + 8;

    uint4 qf[8];
#pragma unroll
    for (int kd = 0; kd < 8; ++kd) {
        const int base = r0l * PS_LD + kd * 8 + qd;
        qf[kd].x = __float_as_uint(Ps[base]);
        qf[kd].y = __float_as_uint(Ps[base + 8 * PS_LD]);
        qf[kd].z = __float_as_uint(Ps[base + 4]);
        qf[kd].w = __float_as_uint(Ps[base + 8 * PS_LD + 4]);
    }

    // store K(0) to smem; load V(0) to regs
#pragma unroll
    for (int i = 0; i < 8; ++i) {
        int f = tid + i * 256, r = f >> 4, c4 = (f & 15) << 2;
        *(float4*)&Ks[r * KS_LD + c4] = kr[i];
    }
#pragma unroll
    for (int i = 0; i < 8; ++i) {
        int f = tid + i * 256, r = f >> 4, c4 = (f & 15) << 2;
        vr[i] = *(const float4*)(Vg + (size_t)r * QKV_LD + c4);
    }
    __syncthreads();

    float m0 = -1e30f, m1 = -1e30f, l0 = 0.f, l1 = 0.f;
    float4 o[8];
#pragma unroll
    for (int nt = 0; nt < 8; ++nt) o[nt] = make_float4(0.f, 0.f, 0.f, 0.f);

    for (int jt = 0; jt <= qt; ++jt) {
        const bool more = (jt < qt);

        // stage V(jt) to smem; issue K(jt+1) loads (hide under S-compute)
#pragma unroll
        for (int i = 0; i < 8; ++i) {
            int f = tid + i * 256, r = f >> 4, c4 = (f & 15) << 2;
            *(float4*)&Vs[r * VS_LD2 + c4] = vr[i];
        }
        if (more) {
            const float* Kt = Kg + (size_t)(jt + 1) * 128 * QKV_LD;
#pragma unroll
            for (int i = 0; i < 8; ++i) {
                int f = tid + i * 256, r = f >> 4, c4 = (f & 15) << 2;
                kr[i] = *(const float4*)(Kt + (size_t)r * QKV_LD + c4);
            }
        }

        // ---- S = (Q/8) K^T ----
        float4 s[16];
#pragma unroll
        for (int nt = 0; nt < 16; ++nt) {
            float4 a4 = make_float4(0.f, 0.f, 0.f, 0.f);
#pragma unroll
            for (int kd = 0; kd < 8; ++kd) {
                uint2 bf;
                const int kbase = (nt * 8 + g) * KS_LD + kd * 8 + qd;
                bf.x = __float_as_uint(Ks[kbase]);
                bf.y = __float_as_uint(Ks[kbase + 4]);
                MMA_TF32V(a4, qf[kd], bf);
            }
            s[nt] = a4;
        }

        // ---- mask + row max ----
        const bool diag = (jt == qt);
        float mx0 = -1e30f, mx1 = -1e30f;
#pragma unroll
        for (int nt = 0; nt < 16; ++nt) {
            if (diag) {
                const int c0 = nt * 8 + 2 * qd;
                if (c0 > r0l)     s[nt].x = -1e30f;
                if (c0 + 1 > r0l) s[nt].y = -1e30f;
                if (c0 > r1l)     s[nt].z = -1e30f;
                if (c0 + 1 > r1l) s[nt].w = -1e30f;
            }
            mx0 = fmaxf(mx0, fmaxf(s[nt].x, s[nt].y));
            mx1 = fmaxf(mx1, fmaxf(s[nt].z, s[nt].w));
        }
        mx0 = fmaxf(mx0, __shfl_xor_sync(0xffffffffu, mx0, 1));
        mx0 = fmaxf(mx0, __shfl_xor_sync(0xffffffffu, mx0, 2));
        mx1 = fmaxf(mx1, __shfl_xor_sync(0xffffffffu, mx1, 1));
        mx1 = fmaxf(mx1, __shfl_xor_sync(0xffffffffu, mx1, 2));

        const float mn0 = fmaxf(m0, mx0), mn1 = fmaxf(m1, mx1);
        const float a0 = __expf(m0 - mn0), a1 = __expf(m1 - mn1);
        float sum0 = 0.f, sum1 = 0.f;

        __syncwarp();
#pragma unroll
        for (int nt = 0; nt < 16; ++nt) {
            const float px = __expf(s[nt].x - mn0);
            const float py = __expf(s[nt].y - mn0);
            const float pz = __expf(s[nt].z - mn1);
            const float pw = __expf(s[nt].w - mn1);
            sum0 += px + py;
            sum1 += pz + pw;
            const int cb = nt * 8 + 2 * qd;
            *(float2*)&Ps[r0l * PS_LD + cb] = make_float2(rtf(px), rtf(py));
            *(float2*)&Ps[r1l * PS_LD + cb] = make_float2(rtf(pz), rtf(pw));
        }
        sum0 += __shfl_xor_sync(0xffffffffu, sum0, 1);
        sum0 += __shfl_xor_sync(0xffffffffu, sum0, 2);
        sum1 += __shfl_xor_sync(0xffffffffu, sum1, 1);
        sum1 += __shfl_xor_sync(0xffffffffu, sum1, 2);
        l0 = l0 * a0 + sum0; m0 = mn0;
        l1 = l1 * a1 + sum1; m1 = mn1;

#pragma unroll
        for (int nt = 0; nt < 8; ++nt) {
            o[nt].x *= a0; o[nt].y *= a0;
            o[nt].z *= a1; o[nt].w *= a1;
        }
        __syncwarp();

        __syncthreads();

        // stage K(jt+1) to smem; issue V(jt+1) loads (hide under PV)
        if (more) {
#pragma unroll
            for (int i = 0; i < 8; ++i) {
                int f = tid + i * 256, r = f >> 4, c4 = (f & 15) << 2;
                *(float4*)&Ks[r * KS_LD + c4] = kr[i];
            }
            const float* Vt = Vg + (size_t)(jt + 1) * 128 * QKV_LD;
#pragma unroll
            for (int i = 0; i < 8; ++i) {
                int f = tid + i * 256, r = f >> 4, c4 = (f & 15) << 2;
                vr[i] = *(const float4*)(Vt + (size_t)r * QKV_LD + c4);
            }
        }

        // ---- O += P V ----
#pragma unroll
        for (int kt2 = 0; kt2 < 16; ++kt2) {
            uint4 af;
            const int pbase = r0l * PS_LD + kt2 * 8 + qd;
            af.x = __float_as_uint(Ps[pbase]);
            af.y = __float_as_uint(Ps[pbase + 8 * PS_LD]);
            af.z = __float_as_uint(Ps[pbase + 4]);
            af.w = __float_as_uint(Ps[pbase + 8 * PS_LD + 4]);
#pragma unroll
            for (int nt = 0; nt < 8; ++nt) {
                uint2 bf;
                const int vbase = (kt2 * 8 + qd) * VS_LD2 + nt * 8 + g;
                bf.x = __float_as_uint(Vs[vbase]);
                bf.y = __float_as_uint(Vs[vbase + 4 * VS_LD2]);
                MMA_TF32V(o[nt], af, bf);
            }
        }

        __syncthreads();
    }

    // epilogue — pre-round to tf32 for the Wo GEMM
    const float i0 = 1.f / l0, i1 = 1.f / l1;
    float* Or0 = O + ((size_t)(b * Ss + q0 + r0l)) * Dd + h * HD;
    float* Or1 = Or0 + (size_t)8 * Dd;
#pragma unroll
    for (int nt = 0; nt < 8; ++nt) {
        const int cb = nt * 8 + 2 * qd;
        *(float2*)&Or0[cb] = make_float2(rtf(o[nt].x * i0), rtf(o[nt].y * i0));
        *(float2*)&Or1[cb] = make_float2(rtf(o[nt].z * i1), rtf(o[nt].w * i1));
    }
}

// ---------------- launch ----------------------------------------------------
extern "C" void kernel_launch(void* const* d_in, const int* in_sizes, int n_in,
                              void* d_out, int out_size)
{
    (void)in_sizes; (void)n_in; (void)out_size;
    const float* q  = (const float*)d_in[0];
    const float* k  = (const float*)d_in[1];
    const float* v  = (const float*)d_in[2];
    const float* Wq = (const float*)d_in[3];
    const float* Wk = (const float*)d_in[4];
    const float* Wv = (const float*)d_in[5];
    const float* Wo = (const float*)d_in[6];
    const float* bo = (const float*)d_in[7];
    float* out = (float*)d_out;

    float *Wt, *WoR, *Ain, *QKV, *Obuf;
    cudaGetSymbolAddress((void**)&Wt, g_Wt);
    cudaGetSymbolAddress((void**)&WoR, g_WoR);
    cudaGetSymbolAddress((void**)&Ain, g_Ain);
    cudaGetSymbolAddress((void**)&QKV, g_QKV);
    cudaGetSymbolAddress((void**)&Obuf, g_Obuf);

    pack_round<<<2048, 256>>>(q, k, v, Wq, Wk, Wv, Wo);

    const int gemm_smem = 16384 * sizeof(float);   // 64 KB
    cudaFuncSetAttribute(gemm_mma, cudaFuncAttributeMaxDynamicSharedMemorySize,
                         gemm_smem);

    // fused QKV projections: grid.z selects q/k/v section; outputs tf32-rounded
    gemm_mma<<<dim3(Dd / 128, NTOK / 128, 3), 256, gemm_smem>>>(
        Ain, Wt, QKV, nullptr, Dd, QKV_LD, 1);

    cudaFuncSetAttribute(attn_mma, cudaFuncAttributeMaxDynamicSharedMemorySize,
                         ATT_SMEM);
    attn_mma<<<dim3(Ss / 128, Bb * Hh), 256, ATT_SMEM>>>(QKV, Obuf);

    // out = Obuf @ Wo^T + bo (Obuf and WoR already tf32-rounded)
    gemm_mma<<<dim3(Dd / 128, NTOK / 128, 1), 256, gemm_smem>>>(
        Obuf, WoR, out, bo, Dd, Dd, 0);
}